// round 4
// baseline (speedup 1.0000x reference)
#include <cuda_runtime.h>
#include <cstdint>

#define BB 64
#define TT 512
#define DD 256
#define HH 512
#define NCL 16            // clusters
#define CLC 8             // CTAs per cluster
#define BPC 4             // batches per cluster
#define JPC 64            // columns per CTA

typedef unsigned long long ull;

// Scratch (module-static; no runtime allocs)
__device__ float g_xproj[(size_t)BB * TT * HH];   // 64 MB

__device__ __forceinline__ void cluster_sync_() {
    asm volatile("barrier.cluster.arrive.aligned;\n\t"
                 "barrier.cluster.wait.aligned;\n" ::: "memory");
}
__device__ __forceinline__ void ffma2(ull& acc, ull a, ull b) {
    asm volatile("fma.rn.f32x2 %0, %1, %2, %0;" : "+l"(acc) : "l"(a), "l"(b));
}
__device__ __forceinline__ ull pack2(float x, float y) {
    ull r; asm("mov.b64 %0, {%1, %2};" : "=l"(r) : "f"(x), "f"(y)); return r;
}
__device__ __forceinline__ float2 unpack2(ull v) {
    float2 r; asm("mov.b64 {%0, %1}, %2;" : "=f"(r.x), "=f"(r.y) : "l"(v)); return r;
}
__device__ __forceinline__ uint32_t mapa_(uint32_t addr, uint32_t rank) {
    uint32_t r;
    asm("mapa.shared::cluster.u32 %0, %1, %2;" : "=r"(r) : "r"(addr), "r"(rank));
    return r;
}
__device__ __forceinline__ float ftanh(float x) {
    float xc = fminf(fmaxf(x, -9.f), 9.f);
    float e  = __expf(2.f * xc);
    return 1.f - __fdividef(2.f, e + 1.f);
}

// ---------------------------------------------------------------------------
// Kernel 1: xproj[B*T, H] = inputs[B*T, D] @ Wx[D, H] + b  (f32x2 FMA)
// ---------------------------------------------------------------------------
__global__ void __launch_bounds__(256) xproj_kernel(
    const float* __restrict__ A, const float* __restrict__ Wx,
    const float* __restrict__ bias) {
    __shared__ float As[16][128];
    __shared__ float Bs[16][64];

    const int tid = threadIdx.x;
    const int bm  = blockIdx.x * 128;
    const int bn  = blockIdx.y * 64;
    const int tx  = tid & 15;
    const int ty  = tid >> 4;

    ull acc[4][4];
#pragma unroll
    for (int p = 0; p < 4; ++p)
#pragma unroll
        for (int j = 0; j < 4; ++j) acc[p][j] = 0ull;

    const int m0 = tid >> 2;
    const int q  = tid & 3;
    const int kb = tid >> 4;
    const int jb = tid & 15;

    for (int kt = 0; kt < 16; ++kt) {
        float4 a0 = __ldg((const float4*)(A + (size_t)(bm + m0) * DD + kt * 16) + q);
        float4 a1 = __ldg((const float4*)(A + (size_t)(bm + m0 + 64) * DD + kt * 16) + q);
        float4 bv = __ldg((const float4*)(Wx + (size_t)(kt * 16 + kb) * HH + bn) + jb);
        __syncthreads();
        As[q * 4 + 0][m0] = a0.x; As[q * 4 + 1][m0] = a0.y;
        As[q * 4 + 2][m0] = a0.z; As[q * 4 + 3][m0] = a0.w;
        As[q * 4 + 0][m0 + 64] = a1.x; As[q * 4 + 1][m0 + 64] = a1.y;
        As[q * 4 + 2][m0 + 64] = a1.z; As[q * 4 + 3][m0 + 64] = a1.w;
        *(float4*)&Bs[kb][jb * 4] = bv;
        __syncthreads();
#pragma unroll
        for (int k = 0; k < 16; ++k) {
            ulonglong2 a01 = *(const ulonglong2*)&As[k][ty * 8];
            ulonglong2 a23 = *(const ulonglong2*)&As[k][ty * 8 + 4];
            float4 bq = *(const float4*)&Bs[k][tx * 4];
            ull b0 = pack2(bq.x, bq.x), b1 = pack2(bq.y, bq.y);
            ull b2 = pack2(bq.z, bq.z), b3 = pack2(bq.w, bq.w);
            ffma2(acc[0][0], a01.x, b0); ffma2(acc[0][1], a01.x, b1);
            ffma2(acc[0][2], a01.x, b2); ffma2(acc[0][3], a01.x, b3);
            ffma2(acc[1][0], a01.y, b0); ffma2(acc[1][1], a01.y, b1);
            ffma2(acc[1][2], a01.y, b2); ffma2(acc[1][3], a01.y, b3);
            ffma2(acc[2][0], a23.x, b0); ffma2(acc[2][1], a23.x, b1);
            ffma2(acc[2][2], a23.x, b2); ffma2(acc[2][3], a23.x, b3);
            ffma2(acc[3][0], a23.y, b0); ffma2(acc[3][1], a23.y, b1);
            ffma2(acc[3][2], a23.y, b2); ffma2(acc[3][3], a23.y, b3);
        }
    }

    float4 bb = __ldg((const float4*)(bias + bn) + tx);
#pragma unroll
    for (int p = 0; p < 4; ++p) {
        float2 c0 = unpack2(acc[p][0]), c1 = unpack2(acc[p][1]);
        float2 c2 = unpack2(acc[p][2]), c3 = unpack2(acc[p][3]);
        float4 ve, vo;
        ve.x = c0.x + bb.x; ve.y = c1.x + bb.y; ve.z = c2.x + bb.z; ve.w = c3.x + bb.w;
        vo.x = c0.y + bb.x; vo.y = c1.y + bb.y; vo.z = c2.y + bb.z; vo.w = c3.y + bb.w;
        int row = bm + ty * 8 + p * 2;
        *(float4*)&g_xproj[(size_t)row * HH + bn + tx * 4]       = ve;
        *(float4*)&g_xproj[(size_t)(row + 1) * HH + bn + tx * 4] = vo;
    }
}

// ---------------------------------------------------------------------------
// Kernel 2: persistent scan, 512 threads/CTA, DSMEM exchange, ONE cluster.sync.
//  phase1: acc{2jp,2jp+1}_b += {w,w'} * {h_b,h_b}  (hdup, no packing)
//  phase2: z -> direct st.shared::cluster scatter to all 8 CTAs (ping-pong),
//          warp LN partials scattered the same way; cluster.sync;
//          stats finalize + redundant LN/tanh per CTA into local hdup.
// ---------------------------------------------------------------------------
#define F_WH    0                      // 32768 floats: Wh_s[512][64]
#define F_HDUP  32768                  // 4096  floats: hdup[512][4] as ull{h,h}
#define F_ZST   (32768 + 4096)         // 4096  floats: zstage[2][512][4]
#define F_RED   (F_ZST + 4096)         // 4096  floats: red[(kc*4+b)*64 + j]
#define F_PST   (F_RED + 4096)         // 256   floats: pstage[2][4][16] float2
#define F_SSTAT (F_PST + 256)          // 8     floats: float2[4] (mean, rstd)
#define SCAN_SMEM ((F_SSTAT + 8) * 4)

__global__ void __cluster_dims__(8, 1, 1) __launch_bounds__(512, 1)
scan_kernel(const float* __restrict__ h0, const float* __restrict__ Wh,
            const float* __restrict__ gamma, const float* __restrict__ beta,
            float* __restrict__ out) {
    extern __shared__ float smf[];
    float*  Wh_s  = smf + F_WH;
    ull*    hdupu = (ull*)(smf + F_HDUP);
    float*  zst   = smf + F_ZST;
    float*  redf  = smf + F_RED;
    float*  pst   = smf + F_PST;
    float2* sstat = (float2*)(smf + F_SSTAT);

    const int tid   = threadIdx.x;
    const int rank  = blockIdx.x & 7;
    const int cl    = blockIdx.x >> 3;
    const int jbase = rank * JPC;
    const int bbase = cl * BPC;
    const uint32_t smem_u32 = (uint32_t)__cvta_generic_to_shared(smf);

    // ---- prologue ----
    for (int i = tid; i < 512 * 16; i += 512) {       // Wh column slice
        int k = i >> 4, j4 = i & 15;
        float4 v = __ldg((const float4*)(Wh + (size_t)k * HH + jbase) + j4);
        *(float4*)&Wh_s[(k << 6) + (j4 << 2)] = v;
    }
    {   // hdup from h0: thread tid owns k = tid
        float v0 = h0[(size_t)(bbase + 0) * HH + tid];
        float v1 = h0[(size_t)(bbase + 1) * HH + tid];
        float v2 = h0[(size_t)(bbase + 2) * HH + tid];
        float v3 = h0[(size_t)(bbase + 3) * HH + tid];
        hdupu[tid * 4 + 0] = pack2(v0, v0);
        hdupu[tid * 4 + 1] = pack2(v1, v1);
        hdupu[tid * 4 + 2] = pack2(v2, v2);
        hdupu[tid * 4 + 3] = pack2(v3, v3);
    }
    const float gmj = __ldg(&gamma[tid]);
    const float btj = __ldg(&beta[tid]);

    const int jp = tid & 31;          // column pair 2jp, 2jp+1 (phase 1)
    const int kc = tid >> 5;          // k chunk [32kc, 32kc+32), kc 0..15
    const int b2 = (tid >> 6) & 3;    // phase-2 batch (tid < 256)
    const int j2 = tid & 63;          // phase-2 column
    const int half = (tid >> 5) & 1;  // which 32-col half (phase-2 warp)

    // precomputed DSMEM scatter addresses for z (buf0; buf1 = +8192 imm)
    uint32_t rz[8];
#pragma unroll
    for (int c = 0; c < 8; ++c) rz[c] = 0;
    if (tid < 256) {
        uint32_t zoff = smem_u32 + F_ZST * 4 + (((jbase + j2) << 2) + b2) * 4;
#pragma unroll
        for (int c = 0; c < 8; ++c) rz[c] = mapa_(zoff, c);
    }
    __syncthreads();

    for (int t = 0; t < TT; ++t) {
        const int buf = t & 1;
        float xp = 0.f;
        if (tid < 256)
            xp = __ldcg(&g_xproj[((size_t)(bbase + b2) * TT + t) * HH + jbase + j2]);

        // ---- phase 1: acc_b = {z_2jp, z_2jp+1} partial over k chunk ----
        ull a0 = 0, a1 = 0, a2 = 0, a3 = 0;
        const int k0 = kc << 5;
#pragma unroll
        for (int kk = 0; kk < 32; ++kk) {
            int k = k0 + kk;
            ull w = *(const ull*)&Wh_s[(k << 6) + (jp << 1)];          // LDS.64
            ulonglong2 h01 = *(const ulonglong2*)&hdupu[(k << 2)];     // LDS.128 bcast
            ulonglong2 h23 = *(const ulonglong2*)&hdupu[(k << 2) + 2]; // LDS.128 bcast
            ffma2(a0, w, h01.x);
            ffma2(a1, w, h01.y);
            ffma2(a2, w, h23.x);
            ffma2(a3, w, h23.y);
        }
        {
            ull* red_u = (ull*)redf;
            red_u[((kc << 2) + 0) * 32 + jp] = a0;
            red_u[((kc << 2) + 1) * 32 + jp] = a1;
            red_u[((kc << 2) + 2) * 32 + jp] = a2;
            red_u[((kc << 2) + 3) * 32 + jp] = a3;
        }
        __syncthreads();

        // ---- phase 2 (tid < 256): z, scatter z + LN partials via DSMEM ----
        if (tid < 256) {
            float z = xp;
#pragma unroll
            for (int c = 0; c < 16; ++c)
                z += redf[((c << 2) + b2) * 64 + j2];

            if (buf == 0) {
#pragma unroll
                for (int c = 0; c < 8; ++c)
                    asm volatile("st.shared::cluster.f32 [%0], %1;"
                                 :: "r"(rz[c]), "f"(z) : "memory");
            } else {
#pragma unroll
                for (int c = 0; c < 8; ++c)
                    asm volatile("st.shared::cluster.f32 [%0+8192], %1;"
                                 :: "r"(rz[c]), "f"(z) : "memory");
            }

            float s = z, qs = z * z;
#pragma unroll
            for (int o = 16; o > 0; o >>= 1) {
                s  += __shfl_xor_sync(0xffffffffu, s, o);
                qs += __shfl_xor_sync(0xffffffffu, qs, o);
            }
            if ((tid & 31) == 0) {   // one lane per warp: scatter partial
                ull pv = pack2(s, qs);
                uint32_t poff = smem_u32 + (F_PST + buf * 128) * 4
                              + ((b2 << 4) + (rank << 1) + half) * 8;
#pragma unroll
                for (int c = 0; c < 8; ++c) {
                    uint32_t pa = mapa_(poff, c);
                    asm volatile("st.shared::cluster.u64 [%0], %1;"
                                 :: "r"(pa), "l"(pv) : "memory");
                }
            }
        }
        cluster_sync_();   // all z + partials visible in every CTA's SMEM

        if (tid < 4) {     // finalize LN stats for batch tid
            const float4* pr = (const float4*)&pst[buf * 128 + (tid << 5)];
            float ss = 0.f, qq = 0.f;
#pragma unroll
            for (int i = 0; i < 8; ++i) {
                float4 v = pr[i];
                ss += v.x + v.z; qq += v.y + v.w;
            }
            float mean = ss * (1.0f / 512.0f);
            float var  = qq * (1.0f / 512.0f) - mean * mean;
            sstat[tid] = make_float2(mean, rsqrtf(var + 1e-3f));
        }
        __syncthreads();

        // ---- epilogue: h = tanh(LN(z)) for column tid, all 4 batches ----
        float4 zq = *(const float4*)&zst[buf * 2048 + (tid << 2)];
        float2 st0 = sstat[0], st1 = sstat[1], st2 = sstat[2], st3 = sstat[3];
        float hx = ftanh((zq.x - st0.x) * st0.y * gmj + btj);
        float hy = ftanh((zq.y - st1.x) * st1.y * gmj + btj);
        float hz = ftanh((zq.z - st2.x) * st2.y * gmj + btj);
        float hw = ftanh((zq.w - st3.x) * st3.y * gmj + btj);
        hdupu[(tid << 2) + 0] = pack2(hx, hx);
        hdupu[(tid << 2) + 1] = pack2(hy, hy);
        hdupu[(tid << 2) + 2] = pack2(hz, hz);
        hdupu[(tid << 2) + 3] = pack2(hw, hw);

        if ((tid >> 6) == rank) {  // owner CTA writes its 64 columns
            out[((size_t)(bbase + 0) * TT + t) * HH + tid] = hx;
            out[((size_t)(bbase + 1) * TT + t) * HH + tid] = hy;
            out[((size_t)(bbase + 2) * TT + t) * HH + tid] = hz;
            out[((size_t)(bbase + 3) * TT + t) * HH + tid] = hw;
        }
        __syncthreads();   // hdup ready for next phase 1
    }
}

// ---------------------------------------------------------------------------
extern "C" void kernel_launch(void* const* d_in, const int* in_sizes, int n_in,
                              void* d_out, int out_size) {
    const float* inputs = (const float*)d_in[0];  // [64,512,256]
    const float* h0     = (const float*)d_in[1];  // [64,512]
    const float* Wx     = (const float*)d_in[2];  // [256,512]
    const float* Wh     = (const float*)d_in[3];  // [512,512]
    const float* bias   = (const float*)d_in[4];  // [512]
    const float* gamma  = (const float*)d_in[5];  // [512]
    const float* beta   = (const float*)d_in[6];  // [512]
    float* out = (float*)d_out;                   // [64,512,512]

    cudaFuncSetAttribute(scan_kernel,
                         cudaFuncAttributeMaxDynamicSharedMemorySize, SCAN_SMEM);

    dim3 g1(BB * TT / 128, HH / 64);
    xproj_kernel<<<g1, 256>>>(inputs, Wx, bias);
    scan_kernel<<<NCL * CLC, 512, SCAN_SMEM>>>(h0, Wh, gamma, beta, out);
}

// round 5
// speedup vs baseline: 1.7138x; 1.7138x over previous
#include <cuda_runtime.h>
#include <cstdint>

#define BB 64
#define TT 512
#define DD 256
#define HH 512
#define NCL 16            // clusters
#define CLC 8             // CTAs per cluster
#define BPC 4             // batches per cluster
#define JPC 64            // columns per CTA

typedef unsigned long long ull;

// Scratch (module-static; no runtime allocs)
__device__ float g_xproj[(size_t)BB * TT * HH];   // 64 MB

__device__ __forceinline__ void cluster_sync_() {
    asm volatile("barrier.cluster.arrive.aligned;\n\t"
                 "barrier.cluster.wait.aligned;\n" ::: "memory");
}
__device__ __forceinline__ void ffma2(ull& acc, ull a, ull b) {
    asm volatile("fma.rn.f32x2 %0, %1, %2, %0;" : "+l"(acc) : "l"(a), "l"(b));
}
__device__ __forceinline__ ull pack2(float x, float y) {
    ull r; asm("mov.b64 %0, {%1, %2};" : "=l"(r) : "f"(x), "f"(y)); return r;
}
__device__ __forceinline__ float2 unpack2(ull v) {
    float2 r; asm("mov.b64 {%0, %1}, %2;" : "=f"(r.x), "=f"(r.y) : "l"(v)); return r;
}
__device__ __forceinline__ uint32_t mapa_(uint32_t addr, uint32_t rank) {
    uint32_t r;
    asm("mapa.shared::cluster.u32 %0, %1, %2;" : "=r"(r) : "r"(addr), "r"(rank));
    return r;
}
__device__ __forceinline__ ull ld_dsmem_u64(uint32_t addr) {
    ull v;
    asm volatile("ld.shared::cluster.b64 %0, [%1];" : "=l"(v) : "r"(addr));
    return v;
}
__device__ __forceinline__ float ftanh(float x) {
    float xc = fminf(fmaxf(x, -9.f), 9.f);
    float e  = __expf(2.f * xc);
    return 1.f - __fdividef(2.f, e + 1.f);
}

// ---------------------------------------------------------------------------
// Kernel 1: xproj[B*T, H] = inputs[B*T, D] @ Wx[D, H] + b  (f32x2 FMA)
// ---------------------------------------------------------------------------
__global__ void __launch_bounds__(256) xproj_kernel(
    const float* __restrict__ A, const float* __restrict__ Wx,
    const float* __restrict__ bias) {
    __shared__ float As[16][128];
    __shared__ float Bs[16][64];

    const int tid = threadIdx.x;
    const int bm  = blockIdx.x * 128;
    const int bn  = blockIdx.y * 64;
    const int tx  = tid & 15;
    const int ty  = tid >> 4;

    ull acc[4][4];
#pragma unroll
    for (int p = 0; p < 4; ++p)
#pragma unroll
        for (int j = 0; j < 4; ++j) acc[p][j] = 0ull;

    const int m0 = tid >> 2;
    const int q  = tid & 3;
    const int kb = tid >> 4;
    const int jb = tid & 15;

    for (int kt = 0; kt < 16; ++kt) {
        float4 a0 = __ldg((const float4*)(A + (size_t)(bm + m0) * DD + kt * 16) + q);
        float4 a1 = __ldg((const float4*)(A + (size_t)(bm + m0 + 64) * DD + kt * 16) + q);
        float4 bv = __ldg((const float4*)(Wx + (size_t)(kt * 16 + kb) * HH + bn) + jb);
        __syncthreads();
        As[q * 4 + 0][m0] = a0.x; As[q * 4 + 1][m0] = a0.y;
        As[q * 4 + 2][m0] = a0.z; As[q * 4 + 3][m0] = a0.w;
        As[q * 4 + 0][m0 + 64] = a1.x; As[q * 4 + 1][m0 + 64] = a1.y;
        As[q * 4 + 2][m0 + 64] = a1.z; As[q * 4 + 3][m0 + 64] = a1.w;
        *(float4*)&Bs[kb][jb * 4] = bv;
        __syncthreads();
#pragma unroll
        for (int k = 0; k < 16; ++k) {
            ulonglong2 a01 = *(const ulonglong2*)&As[k][ty * 8];
            ulonglong2 a23 = *(const ulonglong2*)&As[k][ty * 8 + 4];
            float4 bq = *(const float4*)&Bs[k][tx * 4];
            ull b0 = pack2(bq.x, bq.x), b1 = pack2(bq.y, bq.y);
            ull b2 = pack2(bq.z, bq.z), b3 = pack2(bq.w, bq.w);
            ffma2(acc[0][0], a01.x, b0); ffma2(acc[0][1], a01.x, b1);
            ffma2(acc[0][2], a01.x, b2); ffma2(acc[0][3], a01.x, b3);
            ffma2(acc[1][0], a01.y, b0); ffma2(acc[1][1], a01.y, b1);
            ffma2(acc[1][2], a01.y, b2); ffma2(acc[1][3], a01.y, b3);
            ffma2(acc[2][0], a23.x, b0); ffma2(acc[2][1], a23.x, b1);
            ffma2(acc[2][2], a23.x, b2); ffma2(acc[2][3], a23.x, b3);
            ffma2(acc[3][0], a23.y, b0); ffma2(acc[3][1], a23.y, b1);
            ffma2(acc[3][2], a23.y, b2); ffma2(acc[3][3], a23.y, b3);
        }
    }

    float4 bb = __ldg((const float4*)(bias + bn) + tx);
#pragma unroll
    for (int p = 0; p < 4; ++p) {
        float2 c0 = unpack2(acc[p][0]), c1 = unpack2(acc[p][1]);
        float2 c2 = unpack2(acc[p][2]), c3 = unpack2(acc[p][3]);
        float4 ve, vo;
        ve.x = c0.x + bb.x; ve.y = c1.x + bb.y; ve.z = c2.x + bb.z; ve.w = c3.x + bb.w;
        vo.x = c0.y + bb.x; vo.y = c1.y + bb.y; vo.z = c2.y + bb.z; vo.w = c3.y + bb.w;
        int row = bm + ty * 8 + p * 2;
        *(float4*)&g_xproj[(size_t)row * HH + bn + tx * 4]       = ve;
        *(float4*)&g_xproj[(size_t)(row + 1) * HH + bn + tx * 4] = vo;
    }
}

// ---------------------------------------------------------------------------
// Kernel 2: persistent scan. Wh slice in REGISTERS (32 ull/thread). DSMEM
// PULL exchange: each CTA writes its z locally once; after one cluster.sync
// every CTA pulls z + LN partials from peers. No L2 in the chain.
// ---------------------------------------------------------------------------
#define F_HDUP  0        // 4096 floats: hdup[512][4] as ull{h,h}
#define F_RED   4096     // 4096 floats: red[(kc*4+b)*64 + j]
#define F_ZLOC  8192     // 512 floats : zloc[2][64][4]
#define F_PLOC  8704     // 32 floats  : ploc[2][4][2] float2
#define F_PSTL  8736     // 128 floats : pstl[64] float2
#define F_SSTAT 8864     // 8 floats   : float2[4] (mean, rstd)
#define F_TOT   8872

__global__ void __cluster_dims__(8, 1, 1) __launch_bounds__(512, 1)
scan_kernel(const float* __restrict__ h0, const float* __restrict__ Wh,
            const float* __restrict__ gamma, const float* __restrict__ beta,
            float* __restrict__ out) {
    __shared__ __align__(16) float smf[F_TOT];
    ull*    hdupu = (ull*)(smf + F_HDUP);
    float*  redf  = smf + F_RED;
    float2* pstl  = (float2*)(smf + F_PSTL);
    float2* sstat = (float2*)(smf + F_SSTAT);

    const int tid   = threadIdx.x;
    const int rank  = blockIdx.x & 7;
    const int cl    = blockIdx.x >> 3;
    const int jbase = rank * JPC;
    const int bbase = cl * BPC;
    const uint32_t smem_u32 = (uint32_t)__cvta_generic_to_shared(smf);

    const int jp = tid & 31;          // column pair 2jp, 2jp+1 (phase 1)
    const int kc = tid >> 5;          // k chunk [32kc, 32kc+32)
    const int k0 = kc << 5;
    const int b2 = (tid >> 6) & 3;    // phase-2 batch (tid < 256)
    const int j2 = tid & 63;          // phase-2 column
    const int hlf = (tid >> 5) & 1;   // phase-2 half (warp & 1)

    // ---- prologue: weights -> registers (64 regs), hdup, gamma/beta ----
    ull wreg[32];
#pragma unroll
    for (int kk = 0; kk < 32; ++kk)
        wreg[kk] = *(const ull*)&Wh[(size_t)(k0 + kk) * HH + jbase + (jp << 1)];

    {
        float v0 = h0[(size_t)(bbase + 0) * HH + tid];
        float v1 = h0[(size_t)(bbase + 1) * HH + tid];
        float v2 = h0[(size_t)(bbase + 2) * HH + tid];
        float v3 = h0[(size_t)(bbase + 3) * HH + tid];
        hdupu[tid * 4 + 0] = pack2(v0, v0);
        hdupu[tid * 4 + 1] = pack2(v1, v1);
        hdupu[tid * 4 + 2] = pack2(v2, v2);
        hdupu[tid * 4 + 3] = pack2(v3, v3);
    }
    const float gmj = __ldg(&gamma[tid]);
    const float btj = __ldg(&beta[tid]);

    // pull addresses (buf0; buf1 = + immediate)
    const uint32_t zpull = mapa_(smem_u32 + F_ZLOC * 4 + ((tid & 63) << 4),
                                 (uint32_t)(tid >> 6));
    uint32_t ppull = 0;
    if (tid < 64) {
        int pb = tid >> 4, pc = tid & 7, ph = (tid >> 3) & 1;
        ppull = mapa_(smem_u32 + (F_PLOC + pb * 4 + ph * 2) * 4, (uint32_t)pc);
    }
    __syncthreads();

    for (int t = 0; t < TT; ++t) {
        const int buf = t & 1;
        float xp = 0.f;
        if (tid < 256)
            xp = __ldcg(&g_xproj[((size_t)(bbase + b2) * TT + t) * HH + jbase + j2]);

        // ---- phase 1: acc_b{z_2jp, z_2jp+1} over k chunk; weights in regs ----
        ull a0 = 0, a1 = 0, a2 = 0, a3 = 0;
#pragma unroll
        for (int kk = 0; kk < 32; ++kk) {
            int k = k0 + kk;
            ulonglong2 h01 = *(const ulonglong2*)&hdupu[(k << 2)];     // bcast
            ulonglong2 h23 = *(const ulonglong2*)&hdupu[(k << 2) + 2]; // bcast
            ffma2(a0, wreg[kk], h01.x);
            ffma2(a1, wreg[kk], h01.y);
            ffma2(a2, wreg[kk], h23.x);
            ffma2(a3, wreg[kk], h23.y);
        }
        {
            ull* red_u = (ull*)redf;
            red_u[((kc << 2) + 0) * 32 + jp] = a0;
            red_u[((kc << 2) + 1) * 32 + jp] = a1;
            red_u[((kc << 2) + 2) * 32 + jp] = a2;
            red_u[((kc << 2) + 3) * 32 + jp] = a3;
        }
        __syncthreads();

        // ---- phase 2 (tid < 256): z -> local zloc; LN warp partials -> ploc ----
        if (tid < 256) {
            float z = xp;
#pragma unroll
            for (int c = 0; c < 16; ++c)
                z += redf[((c << 2) + b2) * 64 + j2];
            smf[F_ZLOC + buf * 256 + (j2 << 2) + b2] = z;

            float s = z, qs = z * z;
#pragma unroll
            for (int o = 16; o > 0; o >>= 1) {
                s  += __shfl_xor_sync(0xffffffffu, s, o);
                qs += __shfl_xor_sync(0xffffffffu, qs, o);
            }
            if ((tid & 31) == 0)
                *(float2*)&smf[F_PLOC + buf * 16 + b2 * 4 + hlf * 2] =
                    make_float2(s, qs);
        }
        cluster_sync_();   // local writes visible cluster-wide (acq/rel)

        // ---- pulls (DSMEM, 1x traffic) ----
        ull zp01, zp23;
        if (buf == 0) {
            zp01 = ld_dsmem_u64(zpull);
            zp23 = ld_dsmem_u64(zpull + 8);
        } else {
            zp01 = ld_dsmem_u64(zpull + 1024);
            zp23 = ld_dsmem_u64(zpull + 1024 + 8);
        }
        if (tid < 64) {
            ull pv = ld_dsmem_u64(ppull + (buf ? 64u : 0u));
            float2 p = unpack2(pv);
            pstl[tid] = p;
        }
        __syncthreads();

        if (tid < 4) {     // finalize LN stats for batch tid
            const float4* pr = (const float4*)&pstl[tid << 4];
            float ss = 0.f, qq = 0.f;
#pragma unroll
            for (int i = 0; i < 8; ++i) {
                float4 v = pr[i];
                ss += v.x + v.z; qq += v.y + v.w;
            }
            float mean = ss * (1.0f / 512.0f);
            float var  = qq * (1.0f / 512.0f) - mean * mean;
            sstat[tid] = make_float2(mean, rsqrtf(var + 1e-3f));
        }
        __syncthreads();

        // ---- epilogue: h = tanh(LN(z)) for column tid, all 4 batches ----
        float2 z01 = unpack2(zp01), z23 = unpack2(zp23);
        float2 st0 = sstat[0], st1 = sstat[1], st2 = sstat[2], st3 = sstat[3];
        float hx = ftanh((z01.x - st0.x) * st0.y * gmj + btj);
        float hy = ftanh((z01.y - st1.x) * st1.y * gmj + btj);
        float hz = ftanh((z23.x - st2.x) * st2.y * gmj + btj);
        float hw = ftanh((z23.y - st3.x) * st3.y * gmj + btj);
        hdupu[(tid << 2) + 0] = pack2(hx, hx);
        hdupu[(tid << 2) + 1] = pack2(hy, hy);
        hdupu[(tid << 2) + 2] = pack2(hz, hz);
        hdupu[(tid << 2) + 3] = pack2(hw, hw);

        if ((tid >> 6) == rank) {  // owner CTA writes its 64 output columns
            out[((size_t)(bbase + 0) * TT + t) * HH + tid] = hx;
            out[((size_t)(bbase + 1) * TT + t) * HH + tid] = hy;
            out[((size_t)(bbase + 2) * TT + t) * HH + tid] = hz;
            out[((size_t)(bbase + 3) * TT + t) * HH + tid] = hw;
        }
        __syncthreads();   // hdup ready for next phase 1
    }
}

// ---------------------------------------------------------------------------
extern "C" void kernel_launch(void* const* d_in, const int* in_sizes, int n_in,
                              void* d_out, int out_size) {
    const float* inputs = (const float*)d_in[0];  // [64,512,256]
    const float* h0     = (const float*)d_in[1];  // [64,512]
    const float* Wx     = (const float*)d_in[2];  // [256,512]
    const float* Wh     = (const float*)d_in[3];  // [512,512]
    const float* bias   = (const float*)d_in[4];  // [512]
    const float* gamma  = (const float*)d_in[5];  // [512]
    const float* beta   = (const float*)d_in[6];  // [512]
    float* out = (float*)d_out;                   // [64,512,512]

    dim3 g1(BB * TT / 128, HH / 64);
    xproj_kernel<<<g1, 256>>>(inputs, Wx, bias);
    scan_kernel<<<NCL * CLC, 512>>>(h0, Wh, gamma, beta, out);
}

// round 8
// speedup vs baseline: 1.8451x; 1.0766x over previous
#include <cuda_runtime.h>
#include <cstdint>

#define BB 64
#define TT 512
#define DD 256
#define HH 512
#define NCL 16            // clusters
#define CLC 8             // CTAs per cluster
#define BPC 4             // batches per cluster
#define JPC 64            // columns per CTA

typedef unsigned long long ull;

// Scratch (module-static; no runtime allocs)
__device__ float g_xproj[(size_t)BB * TT * HH];   // 64 MB

__device__ __forceinline__ void cluster_sync_() {
    asm volatile("barrier.cluster.arrive.aligned;\n\t"
                 "barrier.cluster.wait.aligned;\n" ::: "memory");
}
__device__ __forceinline__ void ffma2(ull& acc, ull a, ull b) {
    asm volatile("fma.rn.f32x2 %0, %1, %2, %0;" : "+l"(acc) : "l"(a), "l"(b));
}
__device__ __forceinline__ ull add2(ull a, ull b) {
    ull r; asm("add.rn.f32x2 %0, %1, %2;" : "=l"(r) : "l"(a), "l"(b)); return r;
}
__device__ __forceinline__ ull pack2(float x, float y) {
    ull r; asm("mov.b64 %0, {%1, %2};" : "=l"(r) : "f"(x), "f"(y)); return r;
}
__device__ __forceinline__ float2 unpack2(ull v) {
    float2 r; asm("mov.b64 {%0, %1}, %2;" : "=f"(r.x), "=f"(r.y) : "l"(v)); return r;
}
__device__ __forceinline__ uint32_t mapa_(uint32_t addr, uint32_t rank) {
    uint32_t r;
    asm("mapa.shared::cluster.u32 %0, %1, %2;" : "=r"(r) : "r"(addr), "r"(rank));
    return r;
}
__device__ __forceinline__ ull ld_dsmem_u64(uint32_t addr) {
    ull v;
    asm volatile("ld.shared::cluster.b64 %0, [%1];" : "=l"(v) : "r"(addr));
    return v;
}
__device__ __forceinline__ ull ldcg64(const float* p) {
    ull v;
    asm volatile("ld.global.cg.b64 %0, [%1];" : "=l"(v) : "l"(p));
    return v;
}
__device__ __forceinline__ float ftanh(float x) {
    float xc = fminf(fmaxf(x, -9.f), 9.f);
    float e  = __expf(2.f * xc);
    return 1.f - __fdividef(2.f, e + 1.f);
}

// ---------------------------------------------------------------------------
// Kernel 1: xproj[B*T, H] = inputs[B*T, D] @ Wx[D, H] + b  (f32x2 FMA)
// ---------------------------------------------------------------------------
__global__ void __launch_bounds__(256) xproj_kernel(
    const float* __restrict__ A, const float* __restrict__ Wx,
    const float* __restrict__ bias) {
    __shared__ float As[16][128];
    __shared__ float Bs[16][64];

    const int tid = threadIdx.x;
    const int bm  = blockIdx.x * 128;
    const int bn  = blockIdx.y * 64;
    const int tx  = tid & 15;
    const int ty  = tid >> 4;

    ull acc[4][4];
#pragma unroll
    for (int p = 0; p < 4; ++p)
#pragma unroll
        for (int j = 0; j < 4; ++j) acc[p][j] = 0ull;

    const int m0 = tid >> 2;
    const int q  = tid & 3;
    const int kb = tid >> 4;
    const int jb = tid & 15;

    for (int kt = 0; kt < 16; ++kt) {
        float4 a0 = __ldg((const float4*)(A + (size_t)(bm + m0) * DD + kt * 16) + q);
        float4 a1 = __ldg((const float4*)(A + (size_t)(bm + m0 + 64) * DD + kt * 16) + q);
        float4 bv = __ldg((const float4*)(Wx + (size_t)(kt * 16 + kb) * HH + bn) + jb);
        __syncthreads();
        As[q * 4 + 0][m0] = a0.x; As[q * 4 + 1][m0] = a0.y;
        As[q * 4 + 2][m0] = a0.z; As[q * 4 + 3][m0] = a0.w;
        As[q * 4 + 0][m0 + 64] = a1.x; As[q * 4 + 1][m0 + 64] = a1.y;
        As[q * 4 + 2][m0 + 64] = a1.z; As[q * 4 + 3][m0 + 64] = a1.w;
        *(float4*)&Bs[kb][jb * 4] = bv;
        __syncthreads();
#pragma unroll
        for (int k = 0; k < 16; ++k) {
            ulonglong2 a01 = *(const ulonglong2*)&As[k][ty * 8];
            ulonglong2 a23 = *(const ulonglong2*)&As[k][ty * 8 + 4];
            float4 bq = *(const float4*)&Bs[k][tx * 4];
            ull b0 = pack2(bq.x, bq.x), b1 = pack2(bq.y, bq.y);
            ull b2 = pack2(bq.z, bq.z), b3 = pack2(bq.w, bq.w);
            ffma2(acc[0][0], a01.x, b0); ffma2(acc[0][1], a01.x, b1);
            ffma2(acc[0][2], a01.x, b2); ffma2(acc[0][3], a01.x, b3);
            ffma2(acc[1][0], a01.y, b0); ffma2(acc[1][1], a01.y, b1);
            ffma2(acc[1][2], a01.y, b2); ffma2(acc[1][3], a01.y, b3);
            ffma2(acc[2][0], a23.x, b0); ffma2(acc[2][1], a23.x, b1);
            ffma2(acc[2][2], a23.x, b2); ffma2(acc[2][3], a23.x, b3);
            ffma2(acc[3][0], a23.y, b0); ffma2(acc[3][1], a23.y, b1);
            ffma2(acc[3][2], a23.y, b2); ffma2(acc[3][3], a23.y, b3);
        }
    }

    float4 bb = __ldg((const float4*)(bias + bn) + tx);
#pragma unroll
    for (int p = 0; p < 4; ++p) {
        float2 c0 = unpack2(acc[p][0]), c1 = unpack2(acc[p][1]);
        float2 c2 = unpack2(acc[p][2]), c3 = unpack2(acc[p][3]);
        float4 ve, vo;
        ve.x = c0.x + bb.x; ve.y = c1.x + bb.y; ve.z = c2.x + bb.z; ve.w = c3.x + bb.w;
        vo.x = c0.y + bb.x; vo.y = c1.y + bb.y; vo.z = c2.y + bb.z; vo.w = c3.y + bb.w;
        int row = bm + ty * 8 + p * 2;
        *(float4*)&g_xproj[(size_t)row * HH + bn + tx * 4]       = ve;
        *(float4*)&g_xproj[(size_t)(row + 1) * HH + bn + tx * 4] = vo;
    }
}

// ---------------------------------------------------------------------------
// Kernel 2: persistent scan, k-distributed-over-lanes matvec + shuffle-tree
// reduction; weights in registers; one cluster.sync; DSMEM pull exchange.
// Warp w owns cols [4w, 4w+4); lane l covers k = 32i + l (i = 0..15).
// ---------------------------------------------------------------------------
#define F_H4    0        // 2048 floats: h_s[512] float4 {b0,b1,b2,b3}
#define F_ZLOC  2048     // 512 floats : zloc[2][64 j][4 b]
#define F_WPART 2560     // 128 floats : wpart[4 b][16 w] float2
#define F_PLOC  2688     // 16 floats  : ploc[2][4 b] float2
#define F_SSTAT 2704     // 8 floats   : sstat[4 b] float2 (mean, rstd)
#define F_TOT   2712

__global__ void __cluster_dims__(8, 1, 1) __launch_bounds__(512, 1)
scan_kernel(const float* __restrict__ h0, const float* __restrict__ Wh,
            const float* __restrict__ gamma, const float* __restrict__ beta,
            float* __restrict__ out) {
    __shared__ __align__(16) float smf[F_TOT];
    float4* h4s   = (float4*)(smf + F_H4);
    float2* wpart = (float2*)(smf + F_WPART);
    float2* ploc  = (float2*)(smf + F_PLOC);
    float2* sstat = (float2*)(smf + F_SSTAT);

    const int tid   = threadIdx.x;
    const int w     = tid >> 5;
    const int l     = tid & 31;
    const int rank  = blockIdx.x & 7;
    const int cl    = blockIdx.x >> 3;
    const int jbase = rank * JPC;
    const int bbase = cl * BPC;
    const uint32_t smem_u32 = (uint32_t)__cvta_generic_to_shared(smf);

    const int sel  = l >> 4;          // pair ownership after L16
    const int sel2 = (l >> 3) & 1;    // batch-high after L8
    const int sel3 = (l >> 2) & 1;    // batch-low after L4
    const int myp  = sel;                        // final pair
    const int myb  = sel2 * 2 + sel3;            // final batch
    const bool act = ((l & 3) == 0);             // 8 writer lanes per warp

    // ---- prologue: weights -> regs (32 ull), h0 -> h_s, gamma/beta ----
    ull wreg[32];   // [i*2 + p] = {Wh[k][j0], Wh[k][j0+1]}, k = 32i + l
#pragma unroll
    for (int i = 0; i < 16; ++i) {
        int k = i * 32 + l;
        wreg[i * 2 + 0] = *(const ull*)&Wh[(size_t)k * HH + jbase + 4 * w + 0];
        wreg[i * 2 + 1] = *(const ull*)&Wh[(size_t)k * HH + jbase + 4 * w + 2];
    }
    {
        float4 hv;
        hv.x = h0[(size_t)(bbase + 0) * HH + tid];
        hv.y = h0[(size_t)(bbase + 1) * HH + tid];
        hv.z = h0[(size_t)(bbase + 2) * HH + tid];
        hv.w = h0[(size_t)(bbase + 3) * HH + tid];
        h4s[tid] = hv;
    }
    const float gmj = __ldg(&gamma[tid]);
    const float btj = __ldg(&beta[tid]);

    // DSMEM pull addresses (buf 0; buf 1 via byte offsets)
    const uint32_t zpull = mapa_(smem_u32 + F_ZLOC * 4 + ((tid & 63) << 4),
                                 (uint32_t)(tid >> 6));
    uint32_t ppull = 0;
    if (tid < 32)   // lane: c = l&7 (peer), b = l>>3
        ppull = mapa_(smem_u32 + F_PLOC * 4 + (l >> 3) * 8, (uint32_t)(l & 7));

    // xproj address for writer lanes (col j0 = jbase + 4w + 2*myp, batch myb)
    const float* xp_base =
        &g_xproj[((size_t)(bbase + myb) * TT) * HH + jbase + 4 * w + 2 * myp];

    __syncthreads();

    for (int t = 0; t < TT; ++t) {
        const int buf = t & 1;

        // prefetch xproj pair for writer lanes
        ull xp = 0;
        if (act) xp = ldcg64(xp_base + (size_t)t * HH);

        // ---- phase 1: 16 coalesced iterations over k ----
        ull A0 = 0, A1 = 0, A2 = 0, A3 = 0;   // pair 0, batches 0..3
        ull A4 = 0, A5 = 0, A6 = 0, A7 = 0;   // pair 1
#pragma unroll
        for (int i = 0; i < 16; ++i) {
            float4 hv = h4s[i * 32 + l];      // coalesced LDS.128
            ull hb0 = pack2(hv.x, hv.x);
            ull hb1 = pack2(hv.y, hv.y);
            ull hb2 = pack2(hv.z, hv.z);
            ull hb3 = pack2(hv.w, hv.w);
            ffma2(A0, wreg[i * 2 + 0], hb0);
            ffma2(A1, wreg[i * 2 + 0], hb1);
            ffma2(A2, wreg[i * 2 + 0], hb2);
            ffma2(A3, wreg[i * 2 + 0], hb3);
            ffma2(A4, wreg[i * 2 + 1], hb0);
            ffma2(A5, wreg[i * 2 + 1], hb1);
            ffma2(A6, wreg[i * 2 + 1], hb2);
            ffma2(A7, wreg[i * 2 + 1], hb3);
        }

        // ---- shuffle tree: reduce over 32 lanes, redistributing ownership ----
        // L16: keep pair = sel
        ull B0, B1, B2, B3;
        {
            ull g0 = sel ? A0 : A4, k0 = sel ? A4 : A0;
            ull g1 = sel ? A1 : A5, k1 = sel ? A5 : A1;
            ull g2 = sel ? A2 : A6, k2 = sel ? A6 : A2;
            ull g3 = sel ? A3 : A7, k3 = sel ? A7 : A3;
            B0 = add2(k0, __shfl_xor_sync(0xffffffffu, g0, 16));
            B1 = add2(k1, __shfl_xor_sync(0xffffffffu, g1, 16));
            B2 = add2(k2, __shfl_xor_sync(0xffffffffu, g2, 16));
            B3 = add2(k3, __shfl_xor_sync(0xffffffffu, g3, 16));
        }
        // L8: keep batch-high = sel2  (keep {B2,B3} if sel2 else {B0,B1})
        ull C0, C1;
        {
            ull g0 = sel2 ? B0 : B2, k0 = sel2 ? B2 : B0;
            ull g1 = sel2 ? B1 : B3, k1 = sel2 ? B3 : B1;
            C0 = add2(k0, __shfl_xor_sync(0xffffffffu, g0, 8));
            C1 = add2(k1, __shfl_xor_sync(0xffffffffu, g1, 8));
        }
        // L4: keep batch-low = sel3
        ull D;
        {
            ull g = sel3 ? C0 : C1, k = sel3 ? C1 : C0;
            D = add2(k, __shfl_xor_sync(0xffffffffu, g, 4));
        }
        D = add2(D, __shfl_xor_sync(0xffffffffu, D, 2));
        D = add2(D, __shfl_xor_sync(0xffffffffu, D, 1));

        // ---- writer lanes: z = D + xp; stage z + LN partials ----
        float s = 0.f, qs = 0.f;
        if (act) {
            D = add2(D, xp);
            float2 zz = unpack2(D);
            int jloc = 4 * w + 2 * myp;
            smf[F_ZLOC + buf * 256 + (jloc << 2) + myb]       = zz.x;
            smf[F_ZLOC + buf * 256 + ((jloc + 1) << 2) + myb] = zz.y;
            s  = zz.x + zz.y;
            qs = zz.x * zz.x + zz.y * zz.y;
        }
        s  += __shfl_xor_sync(0xffffffffu, s, 16);   // combine pairs
        qs += __shfl_xor_sync(0xffffffffu, qs, 16);
        if (act && l < 16)    // lanes 0,4,8,12: per-(warp,batch) partial
            wpart[myb * 16 + w] = make_float2(s, qs);
        __syncthreads();   // bar1: wpart + zloc(own) complete

        if (w == 0) {   // CTA-level LN partial reduce: 64 entries -> 4
            int bb = l >> 3, wp = (l & 7) * 2;
            float2 e0 = wpart[bb * 16 + wp], e1 = wpart[bb * 16 + wp + 1];
            float ss = e0.x + e1.x, qq = e0.y + e1.y;
#pragma unroll
            for (int o = 1; o <= 4; o <<= 1) {
                ss += __shfl_xor_sync(0xffffffffu, ss, o);
                qq += __shfl_xor_sync(0xffffffffu, qq, o);
            }
            if ((l & 7) == 0)
                ploc[buf * 4 + bb] = make_float2(ss, qq);
        }
        cluster_sync_();   // z + CTA partials visible cluster-wide

        // ---- pulls: z for column tid (2 x b64) + stats (warp 0) ----
        ull zp01 = ld_dsmem_u64(zpull + (uint32_t)buf * 1024u);
        ull zp23 = ld_dsmem_u64(zpull + (uint32_t)buf * 1024u + 8u);
        if (tid < 32) {
            ull pv = ld_dsmem_u64(ppull + (uint32_t)buf * 32u);
            float2 pr = unpack2(pv);
            float ss = pr.x, qq = pr.y;
#pragma unroll
            for (int o = 1; o <= 4; o <<= 1) {
                ss += __shfl_xor_sync(0xffffffffu, ss, o);
                qq += __shfl_xor_sync(0xffffffffu, qq, o);
            }
            if ((l & 7) == 0) {
                float mean = ss * (1.0f / 512.0f);
                float var  = qq * (1.0f / 512.0f) - mean * mean;
                sstat[l >> 3] = make_float2(mean, rsqrtf(var + 1e-3f));
            }
        }
        __syncthreads();   // bar2: sstat ready

        // ---- epilogue: h = tanh(LN(z)) for column tid, all 4 batches ----
        float2 z01 = unpack2(zp01), z23 = unpack2(zp23);
        float2 st0 = sstat[0], st1 = sstat[1], st2 = sstat[2], st3 = sstat[3];
        float4 hq;
        hq.x = ftanh((z01.x - st0.x) * st0.y * gmj + btj);
        hq.y = ftanh((z01.y - st1.x) * st1.y * gmj + btj);
        hq.z = ftanh((z23.x - st2.x) * st2.y * gmj + btj);
        hq.w = ftanh((z23.y - st3.x) * st3.y * gmj + btj);
        h4s[tid] = hq;

        if ((tid >> 6) == rank) {   // owner CTA writes its 64 output columns
            out[((size_t)(bbase + 0) * TT + t) * HH + tid] = hq.x;
            out[((size_t)(bbase + 1) * TT + t) * HH + tid] = hq.y;
            out[((size_t)(bbase + 2) * TT + t) * HH + tid] = hq.z;
            out[((size_t)(bbase + 3) * TT + t) * HH + tid] = hq.w;
        }
        __syncthreads();   // bar3: h_s ready for next phase 1
    }
}

// ---------------------------------------------------------------------------
extern "C" void kernel_launch(void* const* d_in, const int* in_sizes, int n_in,
                              void* d_out, int out_size) {
    const float* inputs = (const float*)d_in[0];  // [64,512,256]
    const float* h0     = (const float*)d_in[1];  // [64,512]
    const float* Wx     = (const float*)d_in[2];  // [256,512]
    const float* Wh     = (const float*)d_in[3];  // [512,512]
    const float* bias   = (const float*)d_in[4];  // [512]
    const float* gamma  = (const float*)d_in[5];  // [512]
    const float* beta   = (const float*)d_in[6];  // [512]
    float* out = (float*)d_out;                   // [64,512,512]

    dim3 g1(BB * TT / 128, HH / 64);
    xproj_kernel<<<g1, 256>>>(inputs, Wx, bias);
    scan_kernel<<<NCL * CLC, 512>>>(h0, Wh, gamma, beta, out);
}

// round 10
// speedup vs baseline: 1.8770x; 1.0173x over previous
#include <cuda_runtime.h>
#include <cstdint>

#define BB 64
#define TT 512
#define DD 256
#define HH 512
#define NCL 16            // clusters
#define CLC 8             // CTAs per cluster
#define BPC 4             // batches per cluster
#define JPC 64            // columns per CTA

typedef unsigned long long ull;

// Scratch (module-static; no runtime allocs)
__device__ float g_xproj[(size_t)BB * TT * HH];   // 64 MB

__device__ __forceinline__ void cluster_sync_() {
    asm volatile("barrier.cluster.arrive.aligned;\n\t"
                 "barrier.cluster.wait.aligned;\n" ::: "memory");
}
__device__ __forceinline__ void ffma2(ull& acc, ull a, ull b) {
    asm volatile("fma.rn.f32x2 %0, %1, %2, %0;" : "+l"(acc) : "l"(a), "l"(b));
}
__device__ __forceinline__ ull add2(ull a, ull b) {
    ull r; asm("add.rn.f32x2 %0, %1, %2;" : "=l"(r) : "l"(a), "l"(b)); return r;
}
__device__ __forceinline__ ull pack2(float x, float y) {
    ull r; asm("mov.b64 %0, {%1, %2};" : "=l"(r) : "f"(x), "f"(y)); return r;
}
__device__ __forceinline__ float2 unpack2(ull v) {
    float2 r; asm("mov.b64 {%0, %1}, %2;" : "=f"(r.x), "=f"(r.y) : "l"(v)); return r;
}
__device__ __forceinline__ uint32_t mapa_(uint32_t addr, uint32_t rank) {
    uint32_t r;
    asm("mapa.shared::cluster.u32 %0, %1, %2;" : "=r"(r) : "r"(addr), "r"(rank));
    return r;
}
__device__ __forceinline__ ull ld_dsmem_u64(uint32_t addr) {
    ull v;
    asm volatile("ld.shared::cluster.b64 %0, [%1];" : "=l"(v) : "r"(addr));
    return v;
}
__device__ __forceinline__ void st_dsmem_u64(uint32_t addr, ull v) {
    asm volatile("st.shared::cluster.u64 [%0], %1;" :: "r"(addr), "l"(v) : "memory");
}
__device__ __forceinline__ ull ldcg64(const float* p) {
    ull v;
    asm volatile("ld.global.cg.b64 %0, [%1];" : "=l"(v) : "l"(p));
    return v;
}
__device__ __forceinline__ float ftanh(float x) {
    float xc = fminf(fmaxf(x, -9.f), 9.f);
    float e  = __expf(2.f * xc);
    return 1.f - __fdividef(2.f, e + 1.f);
}

// ---------------------------------------------------------------------------
// Kernel 1: xproj[B*T, H] = inputs[B*T, D] @ Wx[D, H] + b  (f32x2 FMA)
// ---------------------------------------------------------------------------
__global__ void __launch_bounds__(256) xproj_kernel(
    const float* __restrict__ A, const float* __restrict__ Wx,
    const float* __restrict__ bias) {
    __shared__ float As[16][128];
    __shared__ float Bs[16][64];

    const int tid = threadIdx.x;
    const int bm  = blockIdx.x * 128;
    const int bn  = blockIdx.y * 64;
    const int tx  = tid & 15;
    const int ty  = tid >> 4;

    ull acc[4][4];
#pragma unroll
    for (int p = 0; p < 4; ++p)
#pragma unroll
        for (int j = 0; j < 4; ++j) acc[p][j] = 0ull;

    const int m0 = tid >> 2;
    const int q  = tid & 3;
    const int kb = tid >> 4;
    const int jb = tid & 15;

    for (int kt = 0; kt < 16; ++kt) {
        float4 a0 = __ldg((const float4*)(A + (size_t)(bm + m0) * DD + kt * 16) + q);
        float4 a1 = __ldg((const float4*)(A + (size_t)(bm + m0 + 64) * DD + kt * 16) + q);
        float4 bv = __ldg((const float4*)(Wx + (size_t)(kt * 16 + kb) * HH + bn) + jb);
        __syncthreads();
        As[q * 4 + 0][m0] = a0.x; As[q * 4 + 1][m0] = a0.y;
        As[q * 4 + 2][m0] = a0.z; As[q * 4 + 3][m0] = a0.w;
        As[q * 4 + 0][m0 + 64] = a1.x; As[q * 4 + 1][m0 + 64] = a1.y;
        As[q * 4 + 2][m0 + 64] = a1.z; As[q * 4 + 3][m0 + 64] = a1.w;
        *(float4*)&Bs[kb][jb * 4] = bv;
        __syncthreads();
#pragma unroll
        for (int k = 0; k < 16; ++k) {
            ulonglong2 a01 = *(const ulonglong2*)&As[k][ty * 8];
            ulonglong2 a23 = *(const ulonglong2*)&As[k][ty * 8 + 4];
            float4 bq = *(const float4*)&Bs[k][tx * 4];
            ull b0 = pack2(bq.x, bq.x), b1 = pack2(bq.y, bq.y);
            ull b2 = pack2(bq.z, bq.z), b3 = pack2(bq.w, bq.w);
            ffma2(acc[0][0], a01.x, b0); ffma2(acc[0][1], a01.x, b1);
            ffma2(acc[0][2], a01.x, b2); ffma2(acc[0][3], a01.x, b3);
            ffma2(acc[1][0], a01.y, b0); ffma2(acc[1][1], a01.y, b1);
            ffma2(acc[1][2], a01.y, b2); ffma2(acc[1][3], a01.y, b3);
            ffma2(acc[2][0], a23.x, b0); ffma2(acc[2][1], a23.x, b1);
            ffma2(acc[2][2], a23.x, b2); ffma2(acc[2][3], a23.x, b3);
            ffma2(acc[3][0], a23.y, b0); ffma2(acc[3][1], a23.y, b1);
            ffma2(acc[3][2], a23.y, b2); ffma2(acc[3][3], a23.y, b3);
        }
    }

    float4 bb = __ldg((const float4*)(bias + bn) + tx);
#pragma unroll
    for (int p = 0; p < 4; ++p) {
        float2 c0 = unpack2(acc[p][0]), c1 = unpack2(acc[p][1]);
        float2 c2 = unpack2(acc[p][2]), c3 = unpack2(acc[p][3]);
        float4 ve, vo;
        ve.x = c0.x + bb.x; ve.y = c1.x + bb.y; ve.z = c2.x + bb.z; ve.w = c3.x + bb.w;
        vo.x = c0.y + bb.x; vo.y = c1.y + bb.y; vo.z = c2.y + bb.z; vo.w = c3.y + bb.w;
        int row = bm + ty * 8 + p * 2;
        *(float4*)&g_xproj[(size_t)row * HH + bn + tx * 4]       = ve;
        *(float4*)&g_xproj[(size_t)(row + 1) * HH + bn + tx * 4] = vo;
    }
}

// ---------------------------------------------------------------------------
// Kernel 2: persistent scan (R8 skeleton). Deltas vs R8:
//  - LN partials CTA-reduced then PUSHED to all peers pre-sync (512 B);
//    post-sync stats are local per-warp shuffles -> bar2 deleted.
//  - xproj value prefetched one full step ahead.
//  - out written with st.global.cs (keep g_xproj L2-resident).
// ---------------------------------------------------------------------------
#define F_H4    0        // 2048 floats: h_s[512] float4 {b0,b1,b2,b3}
#define F_ZLOC  2048     // 512 floats : zloc[2][64 j][4 b]
#define F_WPART 2560     // 128 floats : wpart[4 b][16 w] float2
#define F_PLALL 2688     // 128 floats : ploc_all[2][8 cta][4 b] float2
#define F_TOT   2816

__global__ void __cluster_dims__(8, 1, 1) __launch_bounds__(512, 1)
scan_kernel(const float* __restrict__ h0, const float* __restrict__ Wh,
            const float* __restrict__ gamma, const float* __restrict__ beta,
            float* __restrict__ out) {
    __shared__ __align__(16) float smf[F_TOT];
    float4* h4s   = (float4*)(smf + F_H4);
    float2* wpart = (float2*)(smf + F_WPART);

    const int tid   = threadIdx.x;
    const int w     = tid >> 5;
    const int l     = tid & 31;
    const int rank  = blockIdx.x & 7;
    const int cl    = blockIdx.x >> 3;
    const int jbase = rank * JPC;
    const int bbase = cl * BPC;
    const uint32_t smem_u32 = (uint32_t)__cvta_generic_to_shared(smf);

    const int sel  = l >> 4;          // pair ownership after L16
    const int sel2 = (l >> 3) & 1;    // batch-high after L8
    const int sel3 = (l >> 2) & 1;    // batch-low after L4
    const int myp  = sel;
    const int myb  = sel2 * 2 + sel3;
    const bool act = ((l & 3) == 0);  // 8 writer lanes per warp

    // ---- prologue: weights -> regs (32 ull), h0 -> h_s, gamma/beta ----
    ull wreg[32];   // [i*2 + p] = {Wh[k][j0], Wh[k][j0+1]}, k = 32i + l
#pragma unroll
    for (int i = 0; i < 16; ++i) {
        int k = i * 32 + l;
        wreg[i * 2 + 0] = *(const ull*)&Wh[(size_t)k * HH + jbase + 4 * w + 0];
        wreg[i * 2 + 1] = *(const ull*)&Wh[(size_t)k * HH + jbase + 4 * w + 2];
    }
    {
        float4 hv;
        hv.x = h0[(size_t)(bbase + 0) * HH + tid];
        hv.y = h0[(size_t)(bbase + 1) * HH + tid];
        hv.z = h0[(size_t)(bbase + 2) * HH + tid];
        hv.w = h0[(size_t)(bbase + 3) * HH + tid];
        h4s[tid] = hv;
    }
    const float gmj = __ldg(&gamma[tid]);
    const float btj = __ldg(&beta[tid]);

    // DSMEM pull address for z (buf 0; buf 1 via +1024B)
    const uint32_t zpull = mapa_(smem_u32 + F_ZLOC * 4 + ((tid & 63) << 4),
                                 (uint32_t)(tid >> 6));
    // DSMEM push address for LN partials: lane l of warp 0 pushes batch (l&3)
    // of THIS cta into peer (l>>2)'s ploc_all[buf][rank][l&3].
    uint32_t ppush = 0;
    if (w == 0)
        ppush = mapa_(smem_u32 + F_PLALL * 4 + ((rank << 2) + (l & 3)) * 8,
                      (uint32_t)(l >> 2));

    // xproj address for writer lanes (col pair j0, batch myb)
    const float* xp_base =
        &g_xproj[((size_t)(bbase + myb) * TT) * HH + jbase + 4 * w + 2 * myp];

    __syncthreads();

    ull xp_cur = act ? ldcg64(xp_base) : 0ull;   // prefetch t = 0

    for (int t = 0; t < TT; ++t) {
        const int buf = t & 1;

        // ---- phase 1: 16 coalesced iterations over k ----
        ull A0 = 0, A1 = 0, A2 = 0, A3 = 0;   // pair 0, batches 0..3
        ull A4 = 0, A5 = 0, A6 = 0, A7 = 0;   // pair 1
#pragma unroll
        for (int i = 0; i < 16; ++i) {
            float4 hv = h4s[i * 32 + l];      // coalesced LDS.128
            ull hb0 = pack2(hv.x, hv.x);
            ull hb1 = pack2(hv.y, hv.y);
            ull hb2 = pack2(hv.z, hv.z);
            ull hb3 = pack2(hv.w, hv.w);
            ffma2(A0, wreg[i * 2 + 0], hb0);
            ffma2(A1, wreg[i * 2 + 0], hb1);
            ffma2(A2, wreg[i * 2 + 0], hb2);
            ffma2(A3, wreg[i * 2 + 0], hb3);
            ffma2(A4, wreg[i * 2 + 1], hb0);
            ffma2(A5, wreg[i * 2 + 1], hb1);
            ffma2(A6, wreg[i * 2 + 1], hb2);
            ffma2(A7, wreg[i * 2 + 1], hb3);
        }

        // ---- shuffle tree (identical to R8) ----
        ull B0, B1, B2, B3;
        {
            ull g0 = sel ? A0 : A4, k0 = sel ? A4 : A0;
            ull g1 = sel ? A1 : A5, k1 = sel ? A5 : A1;
            ull g2 = sel ? A2 : A6, k2 = sel ? A6 : A2;
            ull g3 = sel ? A3 : A7, k3 = sel ? A7 : A3;
            B0 = add2(k0, __shfl_xor_sync(0xffffffffu, g0, 16));
            B1 = add2(k1, __shfl_xor_sync(0xffffffffu, g1, 16));
            B2 = add2(k2, __shfl_xor_sync(0xffffffffu, g2, 16));
            B3 = add2(k3, __shfl_xor_sync(0xffffffffu, g3, 16));
        }
        ull C0, C1;
        {
            ull g0 = sel2 ? B0 : B2, k0 = sel2 ? B2 : B0;
            ull g1 = sel2 ? B1 : B3, k1 = sel2 ? B3 : B1;
            C0 = add2(k0, __shfl_xor_sync(0xffffffffu, g0, 8));
            C1 = add2(k1, __shfl_xor_sync(0xffffffffu, g1, 8));
        }
        ull D;
        {
            ull g = sel3 ? C0 : C1, k = sel3 ? C1 : C0;
            D = add2(k, __shfl_xor_sync(0xffffffffu, g, 4));
        }
        D = add2(D, __shfl_xor_sync(0xffffffffu, D, 2));
        D = add2(D, __shfl_xor_sync(0xffffffffu, D, 1));

        // ---- writer lanes: z = D + xp; stage z + LN partials ----
        float s = 0.f, qs = 0.f;
        if (act) {
            D = add2(D, xp_cur);
            float2 zz = unpack2(D);
            int jloc = 4 * w + 2 * myp;
            smf[F_ZLOC + buf * 256 + (jloc << 2) + myb]       = zz.x;
            smf[F_ZLOC + buf * 256 + ((jloc + 1) << 2) + myb] = zz.y;
            s  = zz.x + zz.y;
            qs = zz.x * zz.x + zz.y * zz.y;
        }
        s  += __shfl_xor_sync(0xffffffffu, s, 16);   // combine pairs
        qs += __shfl_xor_sync(0xffffffffu, qs, 16);
        if (act && l < 16)    // lanes 0,4,8,12: per-(warp,batch) partial
            wpart[myb * 16 + w] = make_float2(s, qs);

        // prefetch xproj for t+1 (one full step of latency cover)
        if (act) xp_cur = (t + 1 < TT) ? ldcg64(xp_base + (size_t)(t + 1) * HH)
                                       : 0ull;
        __syncthreads();   // bar1: wpart + zloc complete

        if (w == 0) {   // CTA-reduce LN partials + push to all 8 peers
            int b = l & 3, p8 = l >> 2;
            float2 e0 = wpart[b * 16 + p8 * 2];
            float2 e1 = wpart[b * 16 + p8 * 2 + 1];
            float ss = e0.x + e1.x, qq = e0.y + e1.y;
#pragma unroll
            for (int o = 4; o <= 16; o <<= 1) {   // fold 8 lanes of same batch
                ss += __shfl_xor_sync(0xffffffffu, ss, o);
                qq += __shfl_xor_sync(0xffffffffu, qq, o);
            }
            st_dsmem_u64(ppush + (uint32_t)buf * 256u, pack2(ss, qq));
        }
        cluster_sync_();   // z staged + partials pushed, visible everywhere

        // ---- pulls: z for column tid; stats reduced locally per warp ----
        ull zp01 = ld_dsmem_u64(zpull + (uint32_t)buf * 1024u);
        ull zp23 = ld_dsmem_u64(zpull + (uint32_t)buf * 1024u + 8u);

        float m0, m1, m2, m3, r0, r1, r2, r3;
        {
            float2 pr = *(float2*)&smf[F_PLALL + buf * 64 +
                                       (((l >> 2) << 2) + (l & 3)) * 2];
            float ss = pr.x, qq = pr.y;
#pragma unroll
            for (int o = 4; o <= 16; o <<= 1) {   // fold over 8 CTAs
                ss += __shfl_xor_sync(0xffffffffu, ss, o);
                qq += __shfl_xor_sync(0xffffffffu, qq, o);
            }
            float mean = ss * (1.0f / 512.0f);
            float var  = qq * (1.0f / 512.0f) - mean * mean;
            float rstd = rsqrtf(var + 1e-3f);
            int qb = l & 28;
            m0 = __shfl_sync(0xffffffffu, mean, qb | 0);
            m1 = __shfl_sync(0xffffffffu, mean, qb | 1);
            m2 = __shfl_sync(0xffffffffu, mean, qb | 2);
            m3 = __shfl_sync(0xffffffffu, mean, qb | 3);
            r0 = __shfl_sync(0xffffffffu, rstd, qb | 0);
            r1 = __shfl_sync(0xffffffffu, rstd, qb | 1);
            r2 = __shfl_sync(0xffffffffu, rstd, qb | 2);
            r3 = __shfl_sync(0xffffffffu, rstd, qb | 3);
        }

        // ---- epilogue: h = tanh(LN(z)) for column tid, all 4 batches ----
        float2 z01 = unpack2(zp01), z23 = unpack2(zp23);
        float4 hq;
        hq.x = ftanh((z01.x - m0) * r0 * gmj + btj);
        hq.y = ftanh((z01.y - m1) * r1 * gmj + btj);
        hq.z = ftanh((z23.x - m2) * r2 * gmj + btj);
        hq.w = ftanh((z23.y - m3) * r3 * gmj + btj);
        h4s[tid] = hq;

        if ((tid >> 6) == rank) {   // owner CTA: streaming stores (L2-evict)
            __stcs(&out[((size_t)(bbase + 0) * TT + t) * HH + tid], hq.x);
            __stcs(&out[((size_t)(bbase + 1) * TT + t) * HH + tid], hq.y);
            __stcs(&out[((size_t)(bbase + 2) * TT + t) * HH + tid], hq.z);
            __stcs(&out[((size_t)(bbase + 3) * TT + t) * HH + tid], hq.w);
        }
        __syncthreads();   // bar3: h_s ready for next phase 1
    }
}

// ---------------------------------------------------------------------------
extern "C" void kernel_launch(void* const* d_in, const int* in_sizes, int n_in,
                              void* d_out, int out_size) {
    const float* inputs = (const float*)d_in[0];  // [64,512,256]
    const float* h0     = (const float*)d_in[1];  // [64,512]
    const float* Wx     = (const float*)d_in[2];  // [256,512]
    const float* Wh     = (const float*)d_in[3];  // [512,512]
    const float* bias   = (const float*)d_in[4];  // [512]
    const float* gamma  = (const float*)d_in[5];  // [512]
    const float* beta   = (const float*)d_in[6];  // [512]
    float* out = (float*)d_out;                   // [64,512,512]

    dim3 g1(BB * TT / 128, HH / 64);
    xproj_kernel<<<g1, 256>>>(inputs, Wx, bias);
    scan_kernel<<<NCL * CLC, 512>>>(h0, Wh, gamma, beta, out);
}

// round 12
// speedup vs baseline: 2.7674x; 1.4744x over previous
#include <cuda_runtime.h>
#include <cstdint>

#define BB 64
#define TT 512
#define DD 256
#define HH 512
#define NG 32            // groups of 8 CTAs
#define GC 8             // CTAs per group
#define BPG 2            // batches per group

typedef unsigned long long ull;

// Scratch (module-static; no runtime allocs)
__device__ float    g_xproj[(size_t)BB * TT * HH];   // 64 MB
__device__ float    g_z[NG][2][BPG][HH];             // z exchange (ping-pong)
__device__ float2   g_part[NG][2][BPG][GC];          // LN partials
__device__ unsigned g_flag[NG];                      // per-group step counters

__device__ __forceinline__ void ffma2(ull& acc, ull a, ull b) {
    asm volatile("fma.rn.f32x2 %0, %1, %2, %0;" : "+l"(acc) : "l"(a), "l"(b));
}
__device__ __forceinline__ ull add2(ull a, ull b) {
    ull r; asm("add.rn.f32x2 %0, %1, %2;" : "=l"(r) : "l"(a), "l"(b)); return r;
}
__device__ __forceinline__ ull pack2(float x, float y) {
    ull r; asm("mov.b64 %0, {%1, %2};" : "=l"(r) : "f"(x), "f"(y)); return r;
}
__device__ __forceinline__ float2 unpack2(ull v) {
    float2 r; asm("mov.b64 {%0, %1}, %2;" : "=f"(r.x), "=f"(r.y) : "l"(v)); return r;
}
__device__ __forceinline__ ull ldcg64(const float* p) {
    ull v; asm volatile("ld.global.cg.b64 %0, [%1];" : "=l"(v) : "l"(p)); return v;
}
__device__ __forceinline__ float4 ldcg128(const float4* p) {
    float4 v;
    asm volatile("ld.global.cg.v4.f32 {%0, %1, %2, %3}, [%4];"
                 : "=f"(v.x), "=f"(v.y), "=f"(v.z), "=f"(v.w) : "l"(p));
    return v;
}
__device__ __forceinline__ void stcg64(float* p, ull v) {
    asm volatile("st.global.cg.b64 [%0], %1;" :: "l"(p), "l"(v) : "memory");
}
__device__ __forceinline__ void stcg_f2(float2* p, float x, float y) {
    asm volatile("st.global.cg.v2.f32 [%0], {%1, %2};" :: "l"(p), "f"(x), "f"(y) : "memory");
}
__device__ __forceinline__ unsigned ld_acq(const unsigned* p) {
    unsigned v;
    asm volatile("ld.acquire.gpu.global.u32 %0, [%1];" : "=r"(v) : "l"(p) : "memory");
    return v;
}
__device__ __forceinline__ void red_rel_add(unsigned* p, unsigned v) {
    asm volatile("red.release.gpu.global.add.u32 [%0], %1;" :: "l"(p), "r"(v) : "memory");
}
__device__ __forceinline__ float ftanh(float x) {
    float xc = fminf(fmaxf(x, -9.f), 9.f);
    float e  = __expf(2.f * xc);
    return 1.f - __fdividef(2.f, e + 1.f);
}

// ---------------------------------------------------------------------------
// Kernel 1: xproj = inputs @ Wx + b  (f32x2 FMA). Also resets g_flag.
// ---------------------------------------------------------------------------
__global__ void __launch_bounds__(256) xproj_kernel(
    const float* __restrict__ A, const float* __restrict__ Wx,
    const float* __restrict__ bias) {
    __shared__ float As[16][128];
    __shared__ float Bs[16][64];

    const int tid = threadIdx.x;
    if (blockIdx.x == 0 && blockIdx.y == 0 && tid < NG) g_flag[tid] = 0;

    const int bm  = blockIdx.x * 128;
    const int bn  = blockIdx.y * 64;
    const int tx  = tid & 15;
    const int ty  = tid >> 4;

    ull acc[4][4];
#pragma unroll
    for (int p = 0; p < 4; ++p)
#pragma unroll
        for (int j = 0; j < 4; ++j) acc[p][j] = 0ull;

    const int m0 = tid >> 2;
    const int q  = tid & 3;
    const int kb = tid >> 4;
    const int jb = tid & 15;

    for (int kt = 0; kt < 16; ++kt) {
        float4 a0 = __ldg((const float4*)(A + (size_t)(bm + m0) * DD + kt * 16) + q);
        float4 a1 = __ldg((const float4*)(A + (size_t)(bm + m0 + 64) * DD + kt * 16) + q);
        float4 bv = __ldg((const float4*)(Wx + (size_t)(kt * 16 + kb) * HH + bn) + jb);
        __syncthreads();
        As[q * 4 + 0][m0] = a0.x; As[q * 4 + 1][m0] = a0.y;
        As[q * 4 + 2][m0] = a0.z; As[q * 4 + 3][m0] = a0.w;
        As[q * 4 + 0][m0 + 64] = a1.x; As[q * 4 + 1][m0 + 64] = a1.y;
        As[q * 4 + 2][m0 + 64] = a1.z; As[q * 4 + 3][m0 + 64] = a1.w;
        *(float4*)&Bs[kb][jb * 4] = bv;
        __syncthreads();
#pragma unroll
        for (int k = 0; k < 16; ++k) {
            ulonglong2 a01 = *(const ulonglong2*)&As[k][ty * 8];
            ulonglong2 a23 = *(const ulonglong2*)&As[k][ty * 8 + 4];
            float4 bq = *(const float4*)&Bs[k][tx * 4];
            ull b0 = pack2(bq.x, bq.x), b1 = pack2(bq.y, bq.y);
            ull b2 = pack2(bq.z, bq.z), b3 = pack2(bq.w, bq.w);
            ffma2(acc[0][0], a01.x, b0); ffma2(acc[0][1], a01.x, b1);
            ffma2(acc[0][2], a01.x, b2); ffma2(acc[0][3], a01.x, b3);
            ffma2(acc[1][0], a01.y, b0); ffma2(acc[1][1], a01.y, b1);
            ffma2(acc[1][2], a01.y, b2); ffma2(acc[1][3], a01.y, b3);
            ffma2(acc[2][0], a23.x, b0); ffma2(acc[2][1], a23.x, b1);
            ffma2(acc[2][2], a23.x, b2); ffma2(acc[2][3], a23.x, b3);
            ffma2(acc[3][0], a23.y, b0); ffma2(acc[3][1], a23.y, b1);
            ffma2(acc[3][2], a23.y, b2); ffma2(acc[3][3], a23.y, b3);
        }
    }

    float4 bb = __ldg((const float4*)(bias + bn) + tx);
#pragma unroll
    for (int p = 0; p < 4; ++p) {
        float2 c0 = unpack2(acc[p][0]), c1 = unpack2(acc[p][1]);
        float2 c2 = unpack2(acc[p][2]), c3 = unpack2(acc[p][3]);
        float4 ve, vo;
        ve.x = c0.x + bb.x; ve.y = c1.x + bb.y; ve.z = c2.x + bb.z; ve.w = c3.x + bb.w;
        vo.x = c0.y + bb.x; vo.y = c1.y + bb.y; vo.z = c2.y + bb.z; vo.w = c3.y + bb.w;
        int row = bm + ty * 8 + p * 2;
        *(float4*)&g_xproj[(size_t)row * HH + bn + tx * 4]       = ve;
        *(float4*)&g_xproj[(size_t)(row + 1) * HH + bn + tx * 4] = vo;
    }
}

// ---------------------------------------------------------------------------
// Kernel 2: persistent scan, NO clusters. 256 CTAs x 256 thr (2 CTAs/SM).
// Group of 8 CTAs owns 2 batches; CTA owns 64 cols. Weights: half regs,
// half SMEM. Exchange via L2 (.cg); sync via L2 flag counter (release/acquire).
// While one CTA spins/waits, the co-resident CTA computes -> S hidden.
// ---------------------------------------------------------------------------
#define F_WS    0        // 16384 floats (8192 ull): weight k-half [w][cp][256 k']
#define F_H2    16384    // 1024 floats: h2[512] float2 {b0,b1}
#define F_WPART 17408    // 32 floats  : wpart[2 b][8 w] float2
#define F_TOT   17440
#define SCAN_SMEM (F_TOT * 4)

__global__ void __launch_bounds__(256, 2) scan_kernel(
    const float* __restrict__ h0, const float* __restrict__ Wh,
    const float* __restrict__ gamma, const float* __restrict__ beta,
    float* __restrict__ out) {
    extern __shared__ float smf[];
    ull*    ws    = (ull*)(smf + F_WS);
    float2* h2s   = (float2*)(smf + F_H2);
    float2* wpart = (float2*)(smf + F_WPART);

    const int tid   = threadIdx.x;
    const int w     = tid >> 5;
    const int l     = tid & 31;
    const int g     = blockIdx.x >> 3;
    const int rank  = blockIdx.x & 7;
    const int jbase = rank * 64;
    const int bbase = g * BPG;

    const int  sel  = l >> 4;          // col-pair-group bit (after L16)
    const int  sel2 = (l >> 3) & 1;    // col-pair bit (after L8)
    const int  sel3 = (l >> 2) & 1;    // batch bit (after L4)
    const bool act  = ((l & 3) == 0);  // 8 writer lanes per warp

    // ---- prologue ----
    // weights k<256 -> registers (col-pairs), k>=256 -> SMEM (conflict-free)
    ull wreg[32];
#pragma unroll
    for (int i = 0; i < 8; ++i)
#pragma unroll
        for (int cp = 0; cp < 4; ++cp)
            wreg[i * 4 + cp] =
                *(const ull*)&Wh[(size_t)(32 * i + l) * HH + jbase + w * 8 + cp * 2];
#pragma unroll
    for (int i = 0; i < 8; ++i)
#pragma unroll
        for (int cp = 0; cp < 4; ++cp)
            ws[w * 1024 + cp * 256 + 32 * i + l] =
                *(const ull*)&Wh[(size_t)(256 + 32 * i + l) * HH + jbase + w * 8 + cp * 2];

    h2s[2 * tid]     = make_float2(h0[(size_t)(bbase + 0) * HH + 2 * tid],
                                   h0[(size_t)(bbase + 1) * HH + 2 * tid]);
    h2s[2 * tid + 1] = make_float2(h0[(size_t)(bbase + 0) * HH + 2 * tid + 1],
                                   h0[(size_t)(bbase + 1) * HH + 2 * tid + 1]);
    const float gm0 = __ldg(&gamma[2 * tid]),     gm1 = __ldg(&gamma[2 * tid + 1]);
    const float bt0 = __ldg(&beta[2 * tid]),      bt1 = __ldg(&beta[2 * tid + 1]);

    // writer-lane addresses
    const int j0 = jbase + w * 8 + (sel * 2 + sel2) * 2;
    const float* xpb = &g_xproj[((size_t)(bbase + sel3) * TT) * HH + j0];
    float* zdst = &g_z[g][0][sel3][j0];         // buf1 = +BPG*HH floats
    unsigned* flag = &g_flag[g];
    const bool owner = ((tid >> 5) == rank);    // cols 2tid,2tid+1 in [64r,64r+64)

    __syncthreads();
    ull xp = act ? ldcg64(xpb) : 0ull;          // prefetch t = 0

    for (int t = 0; t < TT; ++t) {
        const int buf = t & 1;

        // ---- phase 1: k over lanes (k = 32i + l) ----
        ull A0 = 0, A1 = 0, A2 = 0, A3 = 0;   // [cp0 b0, cp0 b1, cp1 b0, cp1 b1]
        ull A4 = 0, A5 = 0, A6 = 0, A7 = 0;   // [cp2 b0, cp2 b1, cp3 b0, cp3 b1]
#pragma unroll
        for (int i = 0; i < 16; ++i) {
            float2 hv = h2s[i * 32 + l];       // coalesced LDS.64
            ull hb0 = pack2(hv.x, hv.x);
            ull hb1 = pack2(hv.y, hv.y);
            ull w0, w1, w2, w3;
            if (i < 8) {
                w0 = wreg[i * 4 + 0]; w1 = wreg[i * 4 + 1];
                w2 = wreg[i * 4 + 2]; w3 = wreg[i * 4 + 3];
            } else {
                int o = w * 1024 + 32 * (i - 8) + l;
                w0 = ws[o]; w1 = ws[o + 256]; w2 = ws[o + 512]; w3 = ws[o + 768];
            }
            ffma2(A0, w0, hb0); ffma2(A1, w0, hb1);
            ffma2(A2, w1, hb0); ffma2(A3, w1, hb1);
            ffma2(A4, w2, hb0); ffma2(A5, w2, hb1);
            ffma2(A6, w3, hb0); ffma2(A7, w3, hb1);
        }

        // ---- shuffle tree ----
        ull B0, B1, B2, B3;
        {
            ull k0 = sel ? A4 : A0, g0 = sel ? A0 : A4;
            ull k1 = sel ? A5 : A1, g1 = sel ? A1 : A5;
            ull k2 = sel ? A6 : A2, g2 = sel ? A2 : A6;
            ull k3 = sel ? A7 : A3, g3 = sel ? A3 : A7;
            B0 = add2(k0, __shfl_xor_sync(0xffffffffu, g0, 16));
            B1 = add2(k1, __shfl_xor_sync(0xffffffffu, g1, 16));
            B2 = add2(k2, __shfl_xor_sync(0xffffffffu, g2, 16));
            B3 = add2(k3, __shfl_xor_sync(0xffffffffu, g3, 16));
        }
        ull C0, C1;
        {
            ull k0 = sel2 ? B2 : B0, g0 = sel2 ? B0 : B2;
            ull k1 = sel2 ? B3 : B1, g1 = sel2 ? B1 : B3;
            C0 = add2(k0, __shfl_xor_sync(0xffffffffu, g0, 8));
            C1 = add2(k1, __shfl_xor_sync(0xffffffffu, g1, 8));
        }
        ull D;
        {
            ull k = sel3 ? C1 : C0, gv = sel3 ? C0 : C1;
            D = add2(k, __shfl_xor_sync(0xffffffffu, gv, 4));
        }
        D = add2(D, __shfl_xor_sync(0xffffffffu, D, 2));
        D = add2(D, __shfl_xor_sync(0xffffffffu, D, 1));

        // ---- writers: z publish (L2) + LN partials ----
        float s = 0.f, qs = 0.f;
        if (act) {
            D = add2(D, xp);
            float2 zz = unpack2(D);
            stcg64(zdst + buf * (BPG * HH), D);
            s  = zz.x + zz.y;
            qs = zz.x * zz.x + zz.y * zz.y;
        }
        s  += __shfl_xor_sync(0xffffffffu, s, 16);
        qs += __shfl_xor_sync(0xffffffffu, qs, 16);
        s  += __shfl_xor_sync(0xffffffffu, s, 8);
        qs += __shfl_xor_sync(0xffffffffu, qs, 8);
        if (l == 0 || l == 4)                  // lane0: b0, lane4: b1
            wpart[sel3 * 8 + w] = make_float2(s, qs);

        if (act) xp = (t + 1 < TT) ? ldcg64(xpb + (size_t)(t + 1) * HH) : 0ull;
        __syncthreads();   // bar1: z stores + wpart program-order complete

        // ---- warp 0: CTA partial reduce (WARP-UNIFORM), publish, spin ----
        if (w == 0) {
            // All 32 lanes execute; lanes 16-31 duplicate lanes 0-15.
            float2 e = wpart[l & 15];          // [b = (l&15)>>3][w = l&7]
            float ss = e.x, qq = e.y;
#pragma unroll
            for (int o = 1; o <= 4; o <<= 1) { // fold 8 warps of same batch
                ss += __shfl_xor_sync(0xffffffffu, ss, o);
                qq += __shfl_xor_sync(0xffffffffu, qq, o);
            }
            if (l == 0 || l == 8)              // lane0: b0, lane8: b1
                stcg_f2(&g_part[g][buf][l >> 3][rank], ss, qq);
            __syncwarp();
            if (l == 0) red_rel_add(flag, 1u);
            const unsigned target = 8u * (unsigned)(t + 1);
            unsigned v;
            do { v = ld_acq(flag); } while (v < target);
        }
        __syncthreads();   // bar2: whole CTA ordered after all 8 releases

        // ---- pulls: z (2 cols x 2 b) + stats (redundant per thread, .cg) ----
        ull za = ldcg64(&g_z[g][buf][0][2 * tid]);   // {z(2t,b0), z(2t+1,b0)}
        ull zb = ldcg64(&g_z[g][buf][1][2 * tid]);
        float m0, r0, m1, r1;
        {
            const float4* pp = (const float4*)&g_part[g][buf][0][0];
            float ss = 0.f, qq = 0.f;
#pragma unroll
            for (int c = 0; c < 4; ++c) {
                float4 v = ldcg128(pp + c);   // coherent L2 read
                ss += v.x + v.z; qq += v.y + v.w;
            }
            m0 = ss * (1.0f / 512.0f);
            r0 = rsqrtf(qq * (1.0f / 512.0f) - m0 * m0 + 1e-3f);
            ss = 0.f; qq = 0.f;
#pragma unroll
            for (int c = 4; c < 8; ++c) {
                float4 v = ldcg128(pp + c);
                ss += v.x + v.z; qq += v.y + v.w;
            }
            m1 = ss * (1.0f / 512.0f);
            r1 = rsqrtf(qq * (1.0f / 512.0f) - m1 * m1 + 1e-3f);
        }

        // ---- epilogue: h for cols 2tid, 2tid+1, both batches ----
        float2 zA = unpack2(za), zB = unpack2(zb);
        float h00 = ftanh((zA.x - m0) * r0 * gm0 + bt0);   // col 2t,   b0
        float h01 = ftanh((zB.x - m1) * r1 * gm0 + bt0);   // col 2t,   b1
        float h10 = ftanh((zA.y - m0) * r0 * gm1 + bt1);   // col 2t+1, b0
        float h11 = ftanh((zB.y - m1) * r1 * gm1 + bt1);
        h2s[2 * tid]     = make_float2(h00, h01);
        h2s[2 * tid + 1] = make_float2(h10, h11);

        if (owner) {
            __stcs(&out[((size_t)(bbase + 0) * TT + t) * HH + 2 * tid],     h00);
            __stcs(&out[((size_t)(bbase + 0) * TT + t) * HH + 2 * tid + 1], h10);
            __stcs(&out[((size_t)(bbase + 1) * TT + t) * HH + 2 * tid],     h01);
            __stcs(&out[((size_t)(bbase + 1) * TT + t) * HH + 2 * tid + 1], h11);
        }
        __syncthreads();   // bar3: h2s ready for next phase 1
    }
}

// ---------------------------------------------------------------------------
extern "C" void kernel_launch(void* const* d_in, const int* in_sizes, int n_in,
                              void* d_out, int out_size) {
    const float* inputs = (const float*)d_in[0];  // [64,512,256]
    const float* h0     = (const float*)d_in[1];  // [64,512]
    const float* Wx     = (const float*)d_in[2];  // [256,512]
    const float* Wh     = (const float*)d_in[3];  // [512,512]
    const float* bias   = (const float*)d_in[4];  // [512]
    const float* gamma  = (const float*)d_in[5];  // [512]
    const float* beta   = (const float*)d_in[6];  // [512]
    float* out = (float*)d_out;                   // [64,512,512]

    cudaFuncSetAttribute(scan_kernel,
                         cudaFuncAttributeMaxDynamicSharedMemorySize, SCAN_SMEM);

    dim3 g1(BB * TT / 128, HH / 64);
    xproj_kernel<<<g1, 256>>>(inputs, Wx, bias);   // also resets g_flag
    scan_kernel<<<NG * GC, 256, SCAN_SMEM>>>(h0, Wh, gamma, beta, out);
}